// round 3
// baseline (speedup 1.0000x reference)
#include <cuda_runtime.h>
#include <cuda_fp16.h>
#include <cstdint>

#define NT        8192      // M / 64 tiles
#define GRIDSZ    148
#define THREADS   512
#define BM        64
#define KDIM      256
#define NDIM      256

// ---- dynamic smem layout (bytes) ----
#define OFF_C     0                    // 256 fp32 (bias - subtract)
#define OFF_PMAX  1024                 // 8 x 64 fp32
#define OFF_PSUM  3072                 // 8 x 64 fp32
#define OFF_G     5120                 // 64 fp32
#define OFF_A     6144                 // 64 x 256 fp16 = 32768
#define OFF_B     38912                // 256 x 256 fp16 = 131072
#define SMEM_TOTAL 169984

__device__ __forceinline__ uint32_t cvta_smem(const void* p) {
    uint32_t a;
    asm("{ .reg .u64 t; cvta.to.shared.u64 t, %1; cvt.u32.u64 %0, t; }" : "=r"(a) : "l"(p));
    return a;
}

// Swizzle<3,3,3>: row stride 512B (256 fp16). 16B-chunk index ^= row&7.
__device__ __forceinline__ uint32_t sw_off(int row, int col) {
    return (uint32_t)(row * 512 + (((col >> 3) ^ (row & 7)) << 4) + (col & 7) * 2);
}

#define LDSM_X4(r0, r1, r2, r3, addr) \
    asm volatile("ldmatrix.sync.aligned.m8n8.x4.shared.b16 {%0,%1,%2,%3}, [%4];" \
                 : "=r"(r0), "=r"(r1), "=r"(r2), "=r"(r3) : "r"(addr))

#define MMA16816(d, a, b0, b1) \
    asm volatile("mma.sync.aligned.m16n8k16.row.col.f32.f16.f16.f32 " \
                 "{%0,%1,%2,%3}, {%4,%5,%6,%7}, {%8,%9}, {%0,%1,%2,%3};" \
                 : "+f"((d)[0]), "+f"((d)[1]), "+f"((d)[2]), "+f"((d)[3]) \
                 : "r"((a)[0]), "r"((a)[1]), "r"((a)[2]), "r"((a)[3]), \
                   "r"(b0), "r"(b1))

__global__ void __launch_bounds__(THREADS, 1)
fused_gemm_lse_gelu_kernel(const float* __restrict__ x,
                           const float* __restrict__ w,
                           const float* __restrict__ bias,
                           const float* __restrict__ sub,
                           float* __restrict__ out) {
    extern __shared__ char sm[];
    const uint32_t sb = cvta_smem(sm);
    const int tid = threadIdx.x;
    const int wid = tid >> 5;
    const int lane = tid & 31;
    const int mw  = wid & 1;       // M-group: rows mw*32 .. +31
    const int nwg = wid >> 1;      // N-group: cols nwg*32 .. +31

    float* csh  = (float*)(sm + OFF_C);
    float* pmax = (float*)(sm + OFF_PMAX);
    float* psum = (float*)(sm + OFF_PSUM);
    float* gsh  = (float*)(sm + OFF_G);

    // ---- stage W fp32 -> fp16 swizzled SMEM (resident whole kernel) ----
    {
        const float4* wp = (const float4*)w;
#pragma unroll
        for (int i = 0; i < 32; i++) {
            int e = i * 2048 + tid * 4;
            float4 v = wp[i * 512 + tid];
            int n = e >> 8, k = e & 255;
            __half2 p0 = __floats2half2_rn(v.x, v.y);
            __half2 p1 = __floats2half2_rn(v.z, v.w);
            uint32_t addr = sb + OFF_B + sw_off(n, k);
            asm volatile("st.shared.v2.b32 [%0], {%1,%2};"
                         :: "r"(addr), "r"(*(uint32_t*)&p0), "r"(*(uint32_t*)&p1));
        }
    }
    if (tid < 256) csh[tid] = bias[tid] - sub[tid];

    const int t0 = blockIdx.x;

    // ---- prologue: load + convert + stage x(t0); keep fp16 copy in regs ----
    uint32_t h2c[16];
    {
        const float4* xp = (const float4*)(x + (size_t)t0 * (BM * KDIM));
        float4 raw[8];
#pragma unroll
        for (int i = 0; i < 8; i++) raw[i] = __ldcs(xp + i * 512 + tid);
#pragma unroll
        for (int i = 0; i < 8; i++) {
            __half2 a = __floats2half2_rn(raw[i].x, raw[i].y);
            __half2 b = __floats2half2_rn(raw[i].z, raw[i].w);
            h2c[2 * i] = *(uint32_t*)&a;
            h2c[2 * i + 1] = *(uint32_t*)&b;
            int e = i * 2048 + tid * 4;
            uint32_t addr = sb + OFF_A + sw_off(e >> 8, e & 255);
            asm volatile("st.shared.v2.b32 [%0], {%1,%2};"
                         :: "r"(addr), "r"(h2c[2 * i]), "r"(h2c[2 * i + 1]));
        }
    }
    __syncthreads();

    // ---- loop-invariant: bias-sub constants for this thread's 8 columns ----
    float cReg[8];
#pragma unroll
    for (int nt = 0; nt < 4; nt++) {
        cReg[2 * nt]     = csh[nwg * 32 + nt * 8 + (lane & 3) * 2];
        cReg[2 * nt + 1] = csh[nwg * 32 + nt * 8 + (lane & 3) * 2 + 1];
    }

    // ---- ldmatrix lane addresses (k-invariant parts) ----
    const int t4 = lane >> 3;
    const int a_row = mw * 32 + (t4 & 1) * 8 + (lane & 7);
    const uint32_t a_kh = (uint32_t)(t4 >> 1);
    const int b_row = nwg * 32 + (t4 >> 1) * 8 + (lane & 7);
    const uint32_t b_kh = (uint32_t)(t4 & 1);
    const uint32_t aBase0 = sb + OFF_A + (uint32_t)(a_row * 512);
    const uint32_t aBase1 = aBase0 + 16 * 512;
    const uint32_t aRx = (uint32_t)(a_row & 7);
    const uint32_t bBase0 = sb + OFF_B + (uint32_t)(b_row * 512);
    const uint32_t bBase1 = bBase0 + 16 * 512;
    const uint32_t bRx = (uint32_t)(b_row & 7);

    for (int t = t0; t < NT; t += GRIDSZ) {
        // A(t) visible to everyone (barrier from prologue / end of prev iter)

        // ---- issue x(t+1) loads BEFORE the MMA loop (drain under tensor work) ----
        const int tn = t + GRIDSZ;
        const bool hn = tn < NT;
        float4 raw[8];
        if (hn) {
            const float4* xp = (const float4*)(x + (size_t)tn * (BM * KDIM));
#pragma unroll
            for (int i = 0; i < 8; i++) raw[i] = __ldcs(xp + i * 512 + tid);
        }

        // ---- MMA mainloop: 16 k-steps of k16 ----
        float acc[32];
#pragma unroll
        for (int i = 0; i < 32; i++) acc[i] = 0.0f;
#pragma unroll
        for (int ks = 0; ks < 16; ks++) {
            const uint32_t kc = (uint32_t)(2 * ks);
            uint32_t a0[4], a1[4], b0[4], b1[4];
            LDSM_X4(a0[0], a0[1], a0[2], a0[3], aBase0 + (((kc + a_kh) ^ aRx) << 4));
            LDSM_X4(a1[0], a1[1], a1[2], a1[3], aBase1 + (((kc + a_kh) ^ aRx) << 4));
            LDSM_X4(b0[0], b0[1], b0[2], b0[3], bBase0 + (((kc + b_kh) ^ bRx) << 4));
            LDSM_X4(b1[0], b1[1], b1[2], b1[3], bBase1 + (((kc + b_kh) ^ bRx) << 4));
            MMA16816(&acc[0],  a0, b0[0], b0[1]);
            MMA16816(&acc[4],  a0, b0[2], b0[3]);
            MMA16816(&acc[8],  a0, b1[0], b1[1]);
            MMA16816(&acc[12], a0, b1[2], b1[3]);
            MMA16816(&acc[16], a1, b0[0], b0[1]);
            MMA16816(&acc[20], a1, b0[2], b0[3]);
            MMA16816(&acc[24], a1, b1[0], b1[1]);
            MMA16816(&acc[28], a1, b1[2], b1[3]);
        }
        __syncthreads();   // all warps done reading A(t)

        // ---- convert + stage A(t+1) (loads long since landed) ----
        uint32_t h2n[16];
        if (hn) {
#pragma unroll
            for (int i = 0; i < 8; i++) {
                __half2 a = __floats2half2_rn(raw[i].x, raw[i].y);
                __half2 b = __floats2half2_rn(raw[i].z, raw[i].w);
                h2n[2 * i] = *(uint32_t*)&a;
                h2n[2 * i + 1] = *(uint32_t*)&b;
                int e = i * 2048 + tid * 4;
                uint32_t addr = sb + OFF_A + sw_off(e >> 8, e & 255);
                asm volatile("st.shared.v2.b32 [%0], {%1,%2};"
                             :: "r"(addr), "r"(h2n[2 * i]), "r"(h2n[2 * i + 1]));
            }
        }

        // ---- epilogue: per-row max & sum over this warp's 32 cols ----
        {
            float m4[4] = {-3.0e38f, -3.0e38f, -3.0e38f, -3.0e38f};
            float s4[4] = {0.0f, 0.0f, 0.0f, 0.0f};
#pragma unroll
            for (int nt = 0; nt < 4; nt++) {
                float c0 = cReg[2 * nt], c1 = cReg[2 * nt + 1];
#pragma unroll
                for (int mb = 0; mb < 2; mb++) {
                    const float* a = &acc[(mb * 4 + nt) * 4];
                    m4[2 * mb + 0] = fmaxf(m4[2 * mb + 0], fmaxf(a[0] + c0, a[1] + c1));
                    m4[2 * mb + 1] = fmaxf(m4[2 * mb + 1], fmaxf(a[2] + c0, a[3] + c1));
                }
            }
#pragma unroll
            for (int nt = 0; nt < 4; nt++) {
                float c0 = cReg[2 * nt], c1 = cReg[2 * nt + 1];
#pragma unroll
                for (int mb = 0; mb < 2; mb++) {
                    const float* a = &acc[(mb * 4 + nt) * 4];
                    s4[2 * mb + 0] += __expf(a[0] + c0 - m4[2 * mb + 0])
                                    + __expf(a[1] + c1 - m4[2 * mb + 0]);
                    s4[2 * mb + 1] += __expf(a[2] + c0 - m4[2 * mb + 1])
                                    + __expf(a[3] + c1 - m4[2 * mb + 1]);
                }
            }
#pragma unroll
            for (int off = 1; off <= 2; off <<= 1) {
#pragma unroll
                for (int j = 0; j < 4; j++) {
                    float m2 = __shfl_xor_sync(0xFFFFFFFFu, m4[j], off);
                    float s2 = __shfl_xor_sync(0xFFFFFFFFu, s4[j], off);
                    float nm = fmaxf(m4[j], m2);
                    s4[j] = s4[j] * __expf(m4[j] - nm) + s2 * __expf(m2 - nm);
                    m4[j] = nm;
                }
            }
            if ((lane & 3) == 0) {
#pragma unroll
                for (int j = 0; j < 4; j++) {
                    int row = mw * 32 + (j >> 1) * 16 + (j & 1) * 8 + (lane >> 2);
                    pmax[nwg * 64 + row] = m4[j];
                    psum[nwg * 64 + row] = s4[j];
                }
            }
        }
        __syncthreads();

        // ---- combine 8 N-group partials -> lse -> gelu ----
        if (tid < 64) {
            float M = -3.0e38f;
#pragma unroll
            for (int p = 0; p < 8; p++) M = fmaxf(M, pmax[p * 64 + tid]);
            float S = 0.0f;
#pragma unroll
            for (int p = 0; p < 8; p++) S += psum[p * 64 + tid] * __expf(pmax[p * 64 + tid] - M);
            float l = M + __logf(S);
            float u = 0.7978845608028654f * (l + 0.044715f * l * l * l);
            gsh[tid] = 0.5f * l * (1.0f + tanhf(u));
        }
        __syncthreads();

        // ---- store out(t) = gelu(lse(t)) + x(t) from registers; drains under next MMA ----
        {
            float* op = out + (size_t)t * (BM * KDIM);
#pragma unroll
            for (int i = 0; i < 8; i++) {
                int e = i * 2048 + tid * 4;
                float gv = gsh[e >> 8];
                __half2 p0 = *(__half2*)&h2c[2 * i];
                __half2 p1 = *(__half2*)&h2c[2 * i + 1];
                float4 o;
                o.x = __low2float(p0) + gv;
                o.y = __high2float(p0) + gv;
                o.z = __low2float(p1) + gv;
                o.w = __high2float(p1) + gv;
                __stcs((float4*)(op + e), o);
            }
        }
        if (hn) {
#pragma unroll
            for (int i = 0; i < 16; i++) h2c[i] = h2n[i];
        }
        __syncthreads();   // A(t+1) staged & visible for next iteration
    }
}

extern "C" void kernel_launch(void* const* d_in, const int* in_sizes, int n_in,
                              void* d_out, int out_size) {
    const float* x    = (const float*)d_in[0];
    const float* w    = (const float*)d_in[1];
    const float* bias = (const float*)d_in[2];
    const float* sub  = (const float*)d_in[3];
    float* out = (float*)d_out;

    cudaFuncSetAttribute(fused_gemm_lse_gelu_kernel,
                         cudaFuncAttributeMaxDynamicSharedMemorySize, SMEM_TOTAL);
    fused_gemm_lse_gelu_kernel<<<GRIDSZ, THREADS, SMEM_TOTAL>>>(x, w, bias, sub, out);
}

// round 4
// speedup vs baseline: 1.2191x; 1.2191x over previous
#include <cuda_runtime.h>
#include <cuda_fp16.h>
#include <cstdint>

#define NT        8192      // M / 64-row tiles
#define GRIDSZ    148
#define THREADS   512
#define KDIM      256
#define NDIM      256

// ---- dynamic smem layout (bytes) ----
#define OFF_C     0                    // 256 fp32 (bias - subtract)
#define OFF_PMAX  1024                 // 2 halves x (4 x 64) fp32
#define OFF_PSUM  3072
#define OFF_G     5120                 // 2 halves x 64 fp32
#define OFF_A     6144                 // 2 halves x (64 x 256 fp16 = 32768)
#define OFF_B     71680                // 256 x 256 fp16 = 131072
#define SMEM_TOTAL 202752

__device__ __forceinline__ uint32_t cvta_smem(const void* p) {
    uint32_t a;
    asm("{ .reg .u64 t; cvta.to.shared.u64 t, %1; cvt.u32.u64 %0, t; }" : "=r"(a) : "l"(p));
    return a;
}

// Swizzle<3,3,3>: row stride 512B (256 fp16). 16B-chunk index ^= row&7.
__device__ __forceinline__ uint32_t sw_off(int row, int col) {
    return (uint32_t)(row * 512 + (((col >> 3) ^ (row & 7)) << 4) + (col & 7) * 2);
}

#define LDSM_X4(r0, r1, r2, r3, addr) \
    asm volatile("ldmatrix.sync.aligned.m8n8.x4.shared.b16 {%0,%1,%2,%3}, [%4];" \
                 : "=r"(r0), "=r"(r1), "=r"(r2), "=r"(r3) : "r"(addr))

#define MMA16816(d, a, b0, b1) \
    asm volatile("mma.sync.aligned.m16n8k16.row.col.f32.f16.f16.f32 " \
                 "{%0,%1,%2,%3}, {%4,%5,%6,%7}, {%8,%9}, {%0,%1,%2,%3};" \
                 : "+f"((d)[0]), "+f"((d)[1]), "+f"((d)[2]), "+f"((d)[3]) \
                 : "r"((a)[0]), "r"((a)[1]), "r"((a)[2]), "r"((a)[3]), \
                   "r"(b0), "r"(b1))

// per-half named barrier (256 threads each; ids 1 and 2)
#define BARH(id) asm volatile("bar.sync %0, 256;" :: "r"(id) : "memory")

__global__ void __launch_bounds__(THREADS, 1)
fused_gemm_lse_gelu_kernel(const float* __restrict__ x,
                           const float* __restrict__ w,
                           const float* __restrict__ bias,
                           const float* __restrict__ sub,
                           float* __restrict__ out) {
    extern __shared__ char sm[];
    const uint32_t sb = cvta_smem(sm);
    const int tid  = threadIdx.x;
    const int wid  = tid >> 5;
    const int lane = tid & 31;
    const int half = wid >> 3;          // 0 or 1: independent 8-warp pipeline
    const int widh = wid & 7;
    const int tidh = tid & 255;
    const int barid = half + 1;
    const int mw = widh & 1;            // M-group: rows mw*32 .. +31 (of 64)
    const int nw = widh >> 1;           // N-group: cols nw*64 .. +63

    float* csh   = (float*)(sm + OFF_C);
    float* pmaxH = (float*)(sm + OFF_PMAX + half * 1024);
    float* psumH = (float*)(sm + OFF_PSUM + half * 1024);
    float* gshH  = (float*)(sm + OFF_G + half * 256);
    const uint32_t aHalf = sb + OFF_A + (uint32_t)(half * 32768);

    // ---- stage W fp32 -> fp16 swizzled SMEM (whole CTA, resident forever) ----
    {
        const float4* wp = (const float4*)w;
#pragma unroll
        for (int i = 0; i < 32; i++) {
            int e = i * 2048 + tid * 4;
            float4 v = wp[i * 512 + tid];
            int n = e >> 8, k = e & 255;
            __half2 p0 = __floats2half2_rn(v.x, v.y);
            __half2 p1 = __floats2half2_rn(v.z, v.w);
            uint32_t addr = sb + OFF_B + sw_off(n, k);
            asm volatile("st.shared.v2.b32 [%0], {%1,%2};"
                         :: "r"(addr), "r"(*(uint32_t*)&p0), "r"(*(uint32_t*)&p1));
        }
    }
    if (tid < 256) csh[tid] = bias[tid] - sub[tid];
    __syncthreads();   // B + csh visible; halves never full-sync again

    const int t0 = 2 * blockIdx.x + half;

    // ---- per-half prologue: load + convert + stage x(t0) ----
    uint32_t h2[32];
    {
        const float4* xp = (const float4*)(x + (size_t)t0 * (64 * KDIM));
#pragma unroll
        for (int i = 0; i < 16; i++) {
            float4 v = __ldcs(xp + i * 256 + tidh);
            __half2 a = __floats2half2_rn(v.x, v.y);
            __half2 b = __floats2half2_rn(v.z, v.w);
            h2[2 * i] = *(uint32_t*)&a;
            h2[2 * i + 1] = *(uint32_t*)&b;
        }
#pragma unroll
        for (int i = 0; i < 16; i++) {
            int e = i * 1024 + tidh * 4;
            uint32_t addr = aHalf + sw_off(e >> 8, e & 255);
            asm volatile("st.shared.v2.b32 [%0], {%1,%2};"
                         :: "r"(addr), "r"(h2[2 * i]), "r"(h2[2 * i + 1]));
        }
    }
    BARH(barid);

    // ---- ldmatrix lane addresses (k-invariant parts) ----
    const int t4 = lane >> 3;
    const int a_row = mw * 32 + (t4 & 1) * 8 + (lane & 7);
    const uint32_t a_kh = (uint32_t)(t4 >> 1);
    const int b_row0 = nw * 64 + (t4 >> 1) * 8 + (lane & 7);
    const uint32_t b_kh = (uint32_t)(t4 & 1);
    const uint32_t aBase0 = aHalf + (uint32_t)(a_row * 512);
    const uint32_t aBase1 = aBase0 + 16 * 512;
    const uint32_t aRx = (uint32_t)(a_row & 7);
    uint32_t bBase[4], bRx[4];
#pragma unroll
    for (int ng = 0; ng < 4; ng++) {
        int br = b_row0 + ng * 16;
        bBase[ng] = sb + OFF_B + (uint32_t)(br * 512);
        bRx[ng] = (uint32_t)(br & 7);
    }

    for (int t = t0; t < NT; t += 2 * GRIDSZ) {
        // A(t) staged & visible (barrier at loop end / prologue)

        float acc[64];
#pragma unroll
        for (int i = 0; i < 64; i++) acc[i] = 0.0f;

        // ---- MMA mainloop: 16 k-steps of k16 ----
#pragma unroll
        for (int ks = 0; ks < 16; ks++) {
            const uint32_t kc = (uint32_t)(2 * ks);
            uint32_t a0[4], a1[4];
            LDSM_X4(a0[0], a0[1], a0[2], a0[3], aBase0 + (((kc + a_kh) ^ aRx) << 4));
            LDSM_X4(a1[0], a1[1], a1[2], a1[3], aBase1 + (((kc + a_kh) ^ aRx) << 4));
            uint32_t bf[4][4];
#pragma unroll
            for (int ng = 0; ng < 4; ng++)
                LDSM_X4(bf[ng][0], bf[ng][1], bf[ng][2], bf[ng][3],
                        bBase[ng] + (((kc + b_kh) ^ bRx[ng]) << 4));
#pragma unroll
            for (int ng = 0; ng < 4; ng++) {
                MMA16816(&acc[(ng * 2 + 0) * 4], a0, bf[ng][0], bf[ng][1]);
                MMA16816(&acc[(ng * 2 + 1) * 4], a0, bf[ng][2], bf[ng][3]);
                MMA16816(&acc[(8 + ng * 2 + 0) * 4], a1, bf[ng][0], bf[ng][1]);
                MMA16816(&acc[(8 + ng * 2 + 1) * 4], a1, bf[ng][2], bf[ng][3]);
            }
        }

        // ---- prefetch + convert x(t+1); DRAM latency drains under epilogue ----
        const int tn = t + 2 * GRIDSZ;
        const bool hn = tn < NT;
        if (hn) {
            const float4* xp = (const float4*)(x + (size_t)tn * (64 * KDIM));
#pragma unroll
            for (int i = 0; i < 16; i++) {
                float4 v = __ldcs(xp + i * 256 + tidh);
                __half2 a = __floats2half2_rn(v.x, v.y);
                __half2 b = __floats2half2_rn(v.z, v.w);
                h2[2 * i] = *(uint32_t*)&a;
                h2[2 * i + 1] = *(uint32_t*)&b;
            }
        }

        // ---- epilogue: per-row max & sum over this warp's 64 cols ----
        {
            const int n0 = nw * 64;
            float m4[4] = {-3.0e38f, -3.0e38f, -3.0e38f, -3.0e38f};
            float s4[4] = {0.0f, 0.0f, 0.0f, 0.0f};
#pragma unroll
            for (int nt = 0; nt < 8; nt++) {
                float c0 = csh[n0 + nt * 8 + (lane & 3) * 2];
                float c1 = csh[n0 + nt * 8 + (lane & 3) * 2 + 1];
#pragma unroll
                for (int mb = 0; mb < 2; mb++) {
                    const float* a = &acc[(mb * 8 + nt) * 4];
                    m4[2 * mb + 0] = fmaxf(m4[2 * mb + 0], fmaxf(a[0] + c0, a[1] + c1));
                    m4[2 * mb + 1] = fmaxf(m4[2 * mb + 1], fmaxf(a[2] + c0, a[3] + c1));
                }
            }
#pragma unroll
            for (int nt = 0; nt < 8; nt++) {
                float c0 = csh[n0 + nt * 8 + (lane & 3) * 2];
                float c1 = csh[n0 + nt * 8 + (lane & 3) * 2 + 1];
#pragma unroll
                for (int mb = 0; mb < 2; mb++) {
                    const float* a = &acc[(mb * 8 + nt) * 4];
                    s4[2 * mb + 0] += __expf(a[0] + c0 - m4[2 * mb + 0])
                                    + __expf(a[1] + c1 - m4[2 * mb + 0]);
                    s4[2 * mb + 1] += __expf(a[2] + c0 - m4[2 * mb + 1])
                                    + __expf(a[3] + c1 - m4[2 * mb + 1]);
                }
            }
#pragma unroll
            for (int off = 1; off <= 2; off <<= 1) {
#pragma unroll
                for (int j = 0; j < 4; j++) {
                    float m2 = __shfl_xor_sync(0xFFFFFFFFu, m4[j], off);
                    float s2 = __shfl_xor_sync(0xFFFFFFFFu, s4[j], off);
                    float nm = fmaxf(m4[j], m2);
                    s4[j] = s4[j] * __expf(m4[j] - nm) + s2 * __expf(m2 - nm);
                    m4[j] = nm;
                }
            }
            if ((lane & 3) == 0) {
#pragma unroll
                for (int j = 0; j < 4; j++) {
                    int row = mw * 32 + (j >> 1) * 16 + (j & 1) * 8 + (lane >> 2);
                    pmaxH[nw * 64 + row] = m4[j];
                    psumH[nw * 64 + row] = s4[j];
                }
            }
        }
        BARH(barid);   // all MMA/LDSM done; pmax/psum visible

        // ---- combine 4 N-group partials -> lse -> gelu ----
        if (tidh < 64) {
            float m0 = pmaxH[tidh], m1 = pmaxH[64 + tidh],
                  m2 = pmaxH[128 + tidh], m3 = pmaxH[192 + tidh];
            float M = fmaxf(fmaxf(m0, m1), fmaxf(m2, m3));
            float S = psumH[tidh] * __expf(m0 - M) + psumH[64 + tidh] * __expf(m1 - M)
                    + psumH[128 + tidh] * __expf(m2 - M) + psumH[192 + tidh] * __expf(m3 - M);
            float l = M + __logf(S);
            float u = 0.7978845608028654f * (l + 0.044715f * l * l * l);
            gshH[tidh] = 0.5f * l * (1.0f + tanhf(u));
        }
        BARH(barid);   // gsh visible

        // ---- store out(t) = gelu(lse) + x(t) (x from fp16 A tile) ----
        {
            float* op = out + (size_t)t * (64 * KDIM);
#pragma unroll
            for (int i = 0; i < 16; i++) {
                int e = i * 1024 + tidh * 4;
                int r = e >> 8, c = e & 255;
                uint32_t addr = aHalf + sw_off(r, c);
                uint32_t u0, u1;
                asm volatile("ld.shared.v2.b32 {%0,%1}, [%2];" : "=r"(u0), "=r"(u1) : "r"(addr));
                __half2 p0 = *(__half2*)&u0;
                __half2 p1 = *(__half2*)&u1;
                float gv = gshH[r];
                float4 o;
                o.x = __low2float(p0) + gv;
                o.y = __high2float(p0) + gv;
                o.z = __low2float(p1) + gv;
                o.w = __high2float(p1) + gv;
                __stcs((float4*)(op + e), o);
            }
        }
        BARH(barid);   // store done reading A(t)

        // ---- stage A(t+1) ----
        if (hn) {
#pragma unroll
            for (int i = 0; i < 16; i++) {
                int e = i * 1024 + tidh * 4;
                uint32_t addr = aHalf + sw_off(e >> 8, e & 255);
                asm volatile("st.shared.v2.b32 [%0], {%1,%2};"
                             :: "r"(addr), "r"(h2[2 * i]), "r"(h2[2 * i + 1]));
            }
        }
        BARH(barid);   // A(t+1) visible for next MMA
    }
}

extern "C" void kernel_launch(void* const* d_in, const int* in_sizes, int n_in,
                              void* d_out, int out_size) {
    const float* x    = (const float*)d_in[0];
    const float* w    = (const float*)d_in[1];
    const float* bias = (const float*)d_in[2];
    const float* sub  = (const float*)d_in[3];
    float* out = (float*)d_out;

    cudaFuncSetAttribute(fused_gemm_lse_gelu_kernel,
                         cudaFuncAttributeMaxDynamicSharedMemorySize, SMEM_TOTAL);
    fused_gemm_lse_gelu_kernel<<<GRIDSZ, THREADS, SMEM_TOTAL>>>(x, w, bias, sub, out);
}

// round 5
// speedup vs baseline: 1.3162x; 1.0797x over previous
#include <cuda_runtime.h>
#include <cuda_fp16.h>
#include <cstdint>

#define NT        16384     // M / 32-row tiles
#define GRIDSZ    148
#define THREADS   512
#define KDIM      256
#define NDIM      256
#define LSE_OFF   44.0f

// ---- dynamic smem layout (bytes) ----
#define OFF_C     0                    // 256 fp32 (bias - subtract - LSE_OFF)
#define OFF_PSUM  1024                 // 4 quarters x (4 x 32) fp32 = 2048
#define OFF_G     3072                 // 4 quarters x 32 fp32 = 512
#define OFF_A     4096                 // 4 quarters x (32 x 256 fp16 = 16384)
#define OFF_B     69632                // 256 x 256 fp16 = 131072
#define SMEM_TOTAL 200704

__device__ __forceinline__ uint32_t cvta_smem(const void* p) {
    uint32_t a;
    asm("{ .reg .u64 t; cvta.to.shared.u64 t, %1; cvt.u32.u64 %0, t; }" : "=r"(a) : "l"(p));
    return a;
}

// Swizzle<3,3,3>: row stride 512B (256 fp16). 16B-chunk index ^= row&7.
__device__ __forceinline__ uint32_t sw_off(int row, int col) {
    return (uint32_t)(row * 512 + (((col >> 3) ^ (row & 7)) << 4) + (col & 7) * 2);
}

#define LDSM_X4(r0, r1, r2, r3, addr) \
    asm volatile("ldmatrix.sync.aligned.m8n8.x4.shared.b16 {%0,%1,%2,%3}, [%4];" \
                 : "=r"(r0), "=r"(r1), "=r"(r2), "=r"(r3) : "r"(addr))

#define MMA16816(d, a, b0, b1) \
    asm volatile("mma.sync.aligned.m16n8k16.row.col.f32.f16.f16.f32 " \
                 "{%0,%1,%2,%3}, {%4,%5,%6,%7}, {%8,%9}, {%0,%1,%2,%3};" \
                 : "+f"((d)[0]), "+f"((d)[1]), "+f"((d)[2]), "+f"((d)[3]) \
                 : "r"((a)[0]), "r"((a)[1]), "r"((a)[2]), "r"((a)[3]), \
                   "r"(b0), "r"(b1))

// per-quarter named barrier (128 threads each; ids 1..4)
#define BARQ(id) asm volatile("bar.sync %0, 128;" :: "r"(id) : "memory")

__global__ void __launch_bounds__(THREADS, 1)
fused_gemm_lse_gelu_kernel(const float* __restrict__ x,
                           const float* __restrict__ w,
                           const float* __restrict__ bias,
                           const float* __restrict__ sub,
                           float* __restrict__ out) {
    extern __shared__ char sm[];
    const uint32_t sb = cvta_smem(sm);
    const int tid  = threadIdx.x;
    const int lane = tid & 31;
    const int q    = tid >> 7;          // quarter 0..3: independent 4-warp pipeline
    const int tidq = tid & 127;
    const int nw   = (tid >> 5) & 3;    // warp-in-quarter: N-group cols nw*64..+63
    const int barid = q + 1;

    float* csh   = (float*)(sm + OFF_C);
    float* psumQ = (float*)(sm + OFF_PSUM + q * 512);   // [4 groups][32 rows]
    float* gshQ  = (float*)(sm + OFF_G + q * 128);      // [32 rows]
    const uint32_t aQ = sb + OFF_A + (uint32_t)(q * 16384);

    // ---- stage W fp32 -> fp16 swizzled SMEM (whole CTA, resident forever) ----
    {
        const float4* wp = (const float4*)w;
#pragma unroll
        for (int i = 0; i < 32; i++) {
            int e = i * 2048 + tid * 4;
            float4 v = wp[i * 512 + tid];
            int n = e >> 8, k = e & 255;
            __half2 p0 = __floats2half2_rn(v.x, v.y);
            __half2 p1 = __floats2half2_rn(v.z, v.w);
            uint32_t addr = sb + OFF_B + sw_off(n, k);
            asm volatile("st.shared.v2.b32 [%0], {%1,%2};"
                         :: "r"(addr), "r"(*(uint32_t*)&p0), "r"(*(uint32_t*)&p1));
        }
    }
    if (tid < 256) csh[tid] = bias[tid] - sub[tid] - LSE_OFF;
    __syncthreads();   // B + csh visible; quarters never full-sync again

    const int t0 = 4 * blockIdx.x + q;

    // ---- per-quarter prologue: load + convert + stage x(t0); keep fp16 in regs ----
    uint32_t h2[32];
    {
        const float4* xp = (const float4*)(x + (size_t)t0 * (32 * KDIM));
#pragma unroll
        for (int i = 0; i < 16; i++) {
            float4 v = __ldcs(xp + i * 128 + tidq);
            __half2 a = __floats2half2_rn(v.x, v.y);
            __half2 b = __floats2half2_rn(v.z, v.w);
            h2[2 * i] = *(uint32_t*)&a;
            h2[2 * i + 1] = *(uint32_t*)&b;
        }
#pragma unroll
        for (int i = 0; i < 16; i++) {
            int e = i * 512 + tidq * 4;
            uint32_t addr = aQ + sw_off(e >> 8, e & 255);
            asm volatile("st.shared.v2.b32 [%0], {%1,%2};"
                         :: "r"(addr), "r"(h2[2 * i]), "r"(h2[2 * i + 1]));
        }
    }
    BARQ(barid);

    // ---- ldmatrix lane addresses (k-invariant parts) ----
    const int t4 = lane >> 3;
    const int a_row = (t4 & 1) * 8 + (lane & 7);          // rows 0..15 (a0), +16 (a1)
    const uint32_t a_kh = (uint32_t)(t4 >> 1);
    const int b_row0 = nw * 64 + (t4 >> 1) * 8 + (lane & 7);
    const uint32_t b_kh = (uint32_t)(t4 & 1);
    const uint32_t aBase0 = aQ + (uint32_t)(a_row * 512);
    const uint32_t aBase1 = aBase0 + 16 * 512;
    const uint32_t aRx = (uint32_t)(a_row & 7);
    uint32_t bBase[4], bRx[4];
#pragma unroll
    for (int ng = 0; ng < 4; ng++) {
        int br = b_row0 + ng * 16;
        bBase[ng] = sb + OFF_B + (uint32_t)(br * 512);
        bRx[ng] = (uint32_t)(br & 7);
    }

    for (int t = t0; t < NT; t += 4 * GRIDSZ) {
        // A(t) staged & visible (barrier at loop end / prologue)

        float acc[64];
#pragma unroll
        for (int i = 0; i < 64; i++) acc[i] = 0.0f;

        // ---- MMA mainloop: 16 k-steps of k16; warp = 32 rows x 64 cols ----
#pragma unroll
        for (int ks = 0; ks < 16; ks++) {
            const uint32_t kc = (uint32_t)(2 * ks);
            uint32_t a0[4], a1[4];
            LDSM_X4(a0[0], a0[1], a0[2], a0[3], aBase0 + (((kc + a_kh) ^ aRx) << 4));
            LDSM_X4(a1[0], a1[1], a1[2], a1[3], aBase1 + (((kc + a_kh) ^ aRx) << 4));
            uint32_t bf[4][4];
#pragma unroll
            for (int ng = 0; ng < 4; ng++)
                LDSM_X4(bf[ng][0], bf[ng][1], bf[ng][2], bf[ng][3],
                        bBase[ng] + (((kc + b_kh) ^ bRx[ng]) << 4));
#pragma unroll
            for (int ng = 0; ng < 4; ng++) {
                MMA16816(&acc[(ng * 2 + 0) * 4], a0, bf[ng][0], bf[ng][1]);
                MMA16816(&acc[(ng * 2 + 1) * 4], a0, bf[ng][2], bf[ng][3]);
                MMA16816(&acc[(8 + ng * 2 + 0) * 4], a1, bf[ng][0], bf[ng][1]);
                MMA16816(&acc[(8 + ng * 2 + 1) * 4], a1, bf[ng][2], bf[ng][3]);
            }
        }

        // ---- epilogue: no-max LSE partial sums (bias-sub-44 folded into csh) ----
        {
            const int n0 = nw * 64;
            float s4[4] = {0.0f, 0.0f, 0.0f, 0.0f};
#pragma unroll
            for (int nt = 0; nt < 8; nt++) {
                float c0 = csh[n0 + nt * 8 + (lane & 3) * 2];
                float c1 = csh[n0 + nt * 8 + (lane & 3) * 2 + 1];
#pragma unroll
                for (int mb = 0; mb < 2; mb++) {
                    const float* a = &acc[(mb * 8 + nt) * 4];
                    s4[2 * mb + 0] += __expf(a[0] + c0) + __expf(a[1] + c1);
                    s4[2 * mb + 1] += __expf(a[2] + c0) + __expf(a[3] + c1);
                }
            }
#pragma unroll
            for (int off = 1; off <= 2; off <<= 1) {
#pragma unroll
                for (int j = 0; j < 4; j++)
                    s4[j] += __shfl_xor_sync(0xFFFFFFFFu, s4[j], off);
            }
            if ((lane & 3) == 0) {
#pragma unroll
                for (int j = 0; j < 4; j++) {
                    int row = (j >> 1) * 16 + (j & 1) * 8 + (lane >> 2);
                    psumQ[nw * 32 + row] = s4[j];
                }
            }
        }
        BARQ(barid);   // psum visible; all LDSM of A(t) done

        // ---- combine 4 N-group partials -> lse -> gelu ----
        if (tidq < 32) {
            float S = psumQ[tidq] + psumQ[32 + tidq] + psumQ[64 + tidq] + psumQ[96 + tidq];
            float l = __logf(S) + LSE_OFF;
            float u = 0.7978845608028654f * (l + 0.044715f * l * l * l);
            gshQ[tidq] = 0.5f * l * (1.0f + tanhf(u));
        }
        BARQ(barid);   // gsh visible

        // ---- store out(t) = gelu(lse) + x(t), residual straight from registers ----
        {
            float* op = out + (size_t)t * (32 * KDIM);
#pragma unroll
            for (int i = 0; i < 16; i++) {
                int e = i * 512 + tidq * 4;
                float gv = gshQ[e >> 8];
                __half2 p0 = *(__half2*)&h2[2 * i];
                __half2 p1 = *(__half2*)&h2[2 * i + 1];
                float4 o;
                o.x = __low2float(p0) + gv;
                o.y = __high2float(p0) + gv;
                o.z = __low2float(p1) + gv;
                o.w = __high2float(p1) + gv;
                __stcs((float4*)(op + e), o);
            }
        }

        // ---- load + convert + stage x(t+1) (covered by other quarters' MMA) ----
        const int tn = t + 4 * GRIDSZ;
        if (tn < NT) {
            const float4* xp = (const float4*)(x + (size_t)tn * (32 * KDIM));
#pragma unroll
            for (int i = 0; i < 16; i++) {
                float4 v = __ldcs(xp + i * 128 + tidq);
                __half2 a = __floats2half2_rn(v.x, v.y);
                __half2 b = __floats2half2_rn(v.z, v.w);
                h2[2 * i] = *(uint32_t*)&a;
                h2[2 * i + 1] = *(uint32_t*)&b;
            }
#pragma unroll
            for (int i = 0; i < 16; i++) {
                int e = i * 512 + tidq * 4;
                uint32_t addr = aQ + sw_off(e >> 8, e & 255);
                asm volatile("st.shared.v2.b32 [%0], {%1,%2};"
                             :: "r"(addr), "r"(h2[2 * i]), "r"(h2[2 * i + 1]));
            }
        }
        BARQ(barid);   // A(t+1) visible for next MMA
    }
}

extern "C" void kernel_launch(void* const* d_in, const int* in_sizes, int n_in,
                              void* d_out, int out_size) {
    const float* x    = (const float*)d_in[0];
    const float* w    = (const float*)d_in[1];
    const float* bias = (const float*)d_in[2];
    const float* sub  = (const float*)d_in[3];
    float* out = (float*)d_out;

    cudaFuncSetAttribute(fused_gemm_lse_gelu_kernel,
                         cudaFuncAttributeMaxDynamicSharedMemorySize, SMEM_TOTAL);
    fused_gemm_lse_gelu_kernel<<<GRIDSZ, THREADS, SMEM_TOTAL>>>(x, w, bias, sub, out);
}